// round 6
// baseline (speedup 1.0000x reference)
#include <cuda_runtime.h>
#include <cstdint>

// ---------------------------------------------------------------------------
// CharLSTM  (B=512, T=512, VOCAB=256, EMB=32, HID=128)
//
//   k_prep : blocks 0..255 -> embW[v][hcol] = emb[v]@W_ih^T + b_ih + b_hh
//            block 256     -> int64-vs-int32 input detection
//   k_lstm : 128 persistent CTAs x 4 batch rows x 512 steps, 512 threads.
//            Thread = (hcol, row). Accumulates all 4 gate preacts for its own
//            epilogue item -> no gate exchange, ONE barrier/step, double-
//            buffered h. W_hh: k2[0,54) smem (216KB), k2[54,64) regs.
//            fp32x2 FFMA2 GEMM; 4 warps/SMSP for latency hiding.
// ---------------------------------------------------------------------------

#define VOCAB 256
#define EMB   32
#define HID   128
#define G4    512
#define BATCH 512
#define TLEN  512

#define NBLK  128
#define RPB   4
#define NTHR  512

#define K2S   54          // k-pairs in smem
#define K4S   27          // 4-k chunks in smem
#define K2R   10          // k-pairs in regs per thread per gate
#define K4R   5           // 4-k chunks from regs

// smem layout (bytes)
#define WS_BYTES   (K4S * G4 * 16)     // 221184
#define HB_BYTES   (2 * G4 * 4)        // 4096   h double buffer [2][32k4][4r][4f]
#define TOK_BYTES  (RPB * TLEN * 2)    // 4096   uint16 tokens
#define SMEM_BYTES (WS_BYTES + HB_BYTES + TOK_BYTES)   // 229376 <= 232448

__device__ int    g_is64;
__device__ float4 g_embW[VOCAB * HID];   // [v][hcol] = (i,f,g,o) addend

// ---- f32x2 helpers --------------------------------------------------------
__device__ __forceinline__ unsigned long long ffma2(unsigned long long a,
                                                    unsigned long long b,
                                                    unsigned long long c) {
    unsigned long long d;
    asm("fma.rn.f32x2 %0, %1, %2, %3;" : "=l"(d) : "l"(a), "l"(b), "l"(c));
    return d;
}
__device__ __forceinline__ float lo32(unsigned long long v) {
    return __uint_as_float((unsigned int)v);
}
__device__ __forceinline__ float hi32(unsigned long long v) {
    return __uint_as_float((unsigned int)(v >> 32));
}

// ---- activations (EX2/RCP based, ~2 ulp) ----------------------------------
__device__ __forceinline__ float sigf(float x) {
    return __fdividef(1.0f, 1.0f + __expf(-x));
}
__device__ __forceinline__ float tanhf_fast(float x) {
    return 1.0f - __fdividef(2.0f, __expf(2.0f * x) + 1.0f);
}

// ---------------------------------------------------------------------------
// Prep kernel: embW table (blocks 0..255) + input dtype detect (block 256)
// ---------------------------------------------------------------------------
__global__ void k_prep(const unsigned int* __restrict__ words,
                       const float* __restrict__ emb,
                       const float* __restrict__ W_ih,
                       const float* __restrict__ b_a,
                       const float* __restrict__ b_b) {
    if (blockIdx.x == VOCAB) {
        __shared__ int bad;
        if (threadIdx.x == 0) bad = 0;
        __syncthreads();
        int my = 0;
        for (int i = threadIdx.x; i < 4096; i += 128)
            if (words[2 * i + 1] != 0u) my = 1;
        if (my) bad = 1;
        __syncthreads();
        if (threadIdx.x == 0) g_is64 = bad ? 0 : 1;
        return;
    }
    __shared__ float e_s[EMB];
    int v  = blockIdx.x;
    int hc = threadIdx.x;
    if (threadIdx.x < EMB) e_s[threadIdx.x] = emb[v * EMB + threadIdx.x];
    __syncthreads();
    float acc[4];
#pragma unroll
    for (int q = 0; q < 4; q++) {
        int g = q * HID + hc;
        float s = b_a[g] + b_b[g];
        const float* wr = W_ih + g * EMB;
#pragma unroll
        for (int e = 0; e < EMB; e++) s += wr[e] * e_s[e];
        acc[q] = s;
    }
    g_embW[v * HID + hc] = make_float4(acc[0], acc[1], acc[2], acc[3]);
}

// ---------------------------------------------------------------------------
// Main persistent LSTM + classifier
// ---------------------------------------------------------------------------
extern __shared__ unsigned char smem_raw[];

__global__ void __launch_bounds__(NTHR, 1)
k_lstm(const void* __restrict__ inputs,
       const float* __restrict__ W_hh,
       const float* __restrict__ W_cls,
       const float* __restrict__ b_cls,
       float* __restrict__ out) {

    // wS[k4][gate*128 + hcol] : 16B chunk = W[gate*128+hcol][4k4 .. 4k4+3]
    ulonglong2*     wS  = (ulonglong2*)smem_raw;
    // h buffers: float idx = buf*512 + k4*16 + r*4 + sub  (h element 4k4+sub, row r)
    float*          hbF = (float*)(smem_raw + WS_BYTES);
    unsigned short* tok = (unsigned short*)(smem_raw + WS_BYTES + HB_BYTES);

    const int tid   = threadIdx.x;
    const int rbase = blockIdx.x * RPB;
    const int hcol  = tid >> 2;      // 0..127
    const int r     = tid & 3;       // batch row within block

    // ---- token slab (uint16) ----------------------------------------------
    const int is64 = g_is64;
    for (int i = tid; i < RPB * TLEN; i += NTHR) {
        int rr = i >> 9;
        int t  = i & (TLEN - 1);
        long long gi = (long long)(rbase + rr) * TLEN + t;
        int tk;
        if (is64) tk = (int)((const unsigned int*)inputs)[2 * gi];
        else      tk = ((const int*)inputs)[gi];
        tok[rr * TLEN + t] = (unsigned short)(tk & 255);
    }

    // ---- stage W_hh smem part ---------------------------------------------
    const ulonglong2* W4 = (const ulonglong2*)W_hh;   // [512 rows][32 chunks]
    for (int i = tid; i < K4S * G4; i += NTHR) {
        int k4 = i >> 9;
        int g  = i & 511;
        wS[k4 * G4 + g] = W4[g * 32 + k4];
    }

    // ---- register weights: k2 in [K2S,64) for all 4 gates of this hcol ----
    unsigned long long wr[4][K2R];
    {
        const unsigned long long* Wv = (const unsigned long long*)W_hh;
#pragma unroll
        for (int q = 0; q < 4; q++) {
            const unsigned long long* p = Wv + (q * HID + hcol) * 64 + K2S;
#pragma unroll
            for (int j = 0; j < K2R; j++) wr[q][j] = p[j];
        }
    }

    // ---- zero h buffer 0 ----------------------------------------------------
    for (int i = tid; i < G4; i += NTHR) hbF[i] = 0.0f;

    float c = 0.0f;
    __syncthreads();

    const unsigned short* tp = tok + r * TLEN;
    const ulonglong2* wp = wS + hcol;
    const int hwidx = (hcol >> 2) * 16 + r * 4 + (hcol & 3);

    // =========================== time loop ==================================
    for (int t = 0; t < TLEN; t++) {
        const int cur = t & 1;

        // epilogue addends (L2-resident table; latency hidden under GEMM)
        int tk = tp[t];
        float4 e = g_embW[tk * HID + hcol];

        const ulonglong2* hB = (const ulonglong2*)(hbF + cur * G4);

        unsigned long long a0 = 0, a1 = 0, a2 = 0, a3 = 0;

#pragma unroll
        for (int k4 = 0; k4 < K4S; k4++) {
            ulonglong2 hx = hB[k4 * 4 + r];            // h[4k4..4k4+3][r]
            ulonglong2 w0 = wp[k4 * G4 + 0 * HID];
            ulonglong2 w1 = wp[k4 * G4 + 1 * HID];
            ulonglong2 w2 = wp[k4 * G4 + 2 * HID];
            ulonglong2 w3 = wp[k4 * G4 + 3 * HID];
            a0 = ffma2(w0.x, hx.x, a0);  a0 = ffma2(w0.y, hx.y, a0);
            a1 = ffma2(w1.x, hx.x, a1);  a1 = ffma2(w1.y, hx.y, a1);
            a2 = ffma2(w2.x, hx.x, a2);  a2 = ffma2(w2.y, hx.y, a2);
            a3 = ffma2(w3.x, hx.x, a3);  a3 = ffma2(w3.y, hx.y, a3);
        }
#pragma unroll
        for (int j = 0; j < K4R; j++) {
            ulonglong2 hx = hB[(K4S + j) * 4 + r];
            a0 = ffma2(wr[0][2 * j], hx.x, a0);  a0 = ffma2(wr[0][2 * j + 1], hx.y, a0);
            a1 = ffma2(wr[1][2 * j], hx.x, a1);  a1 = ffma2(wr[1][2 * j + 1], hx.y, a1);
            a2 = ffma2(wr[2][2 * j], hx.x, a2);  a2 = ffma2(wr[2][2 * j + 1], hx.y, a2);
            a3 = ffma2(wr[3][2 * j], hx.x, a3);  a3 = ffma2(wr[3][2 * j + 1], hx.y, a3);
        }

        // ---- local epilogue: 1 item, gates never leave registers -----------
        float ip = lo32(a0) + hi32(a0) + e.x;
        float fp = lo32(a1) + hi32(a1) + e.y;
        float gp = lo32(a2) + hi32(a2) + e.z;
        float op = lo32(a3) + hi32(a3) + e.w;
        float si = sigf(ip), sf = sigf(fp);
        float sg = tanhf_fast(gp), so = sigf(op);
        c = sf * c + si * sg;
        hbF[(cur ^ 1) * G4 + hwidx] = so * tanhf_fast(c);

        __syncthreads();   // h(next) complete before next step reads it
    }

    // =========================== classifier =================================
    // final h in buffer 0. Linearize into tok area (reused as float[512]).
    float* hlin = (float*)tok;
    for (int i = tid; i < RPB * HID; i += NTHR) {
        int rr = i >> 7;
        int k  = i & (HID - 1);
        hlin[rr * HID + k] = hbF[(k >> 2) * 16 + rr * 4 + (k & 3)];
    }
    __syncthreads();

    {
        int v    = tid & 255;            // vocab column
        int half = tid >> 8;             // 0: rows 0,1   1: rows 2,3
        int ra   = 2 * half;
        float bb = b_cls[v];
        float accA = bb, accB = bb;
        const float4* wc = (const float4*)(W_cls + v * HID);
        const float4* hA = (const float4*)(hlin + ra * HID);
        const float4* hBp = (const float4*)(hlin + (ra + 1) * HID);
#pragma unroll 8
        for (int k4 = 0; k4 < HID / 4; k4++) {
            float4 w  = wc[k4];
            float4 va = hA[k4], vb = hBp[k4];
            accA += w.x * va.x + w.y * va.y + w.z * va.z + w.w * va.w;
            accB += w.x * vb.x + w.y * vb.y + w.z * vb.z + w.w * vb.w;
        }
        out[(rbase + ra) * VOCAB + v]     = accA;
        out[(rbase + ra + 1) * VOCAB + v] = accB;
    }
}

// ---------------------------------------------------------------------------
// Host launcher (inputs mapped by element count; bias ambiguity harmless:
// biases only ever used summed).
// ---------------------------------------------------------------------------
extern "C" void kernel_launch(void* const* d_in, const int* in_sizes, int n_in,
                              void* d_out, int out_size) {
    const void*  inputs = nullptr;
    const float* emb = nullptr;
    const float* W_ih = nullptr;
    const float* W_hh = nullptr;
    const float* b_a = nullptr;
    const float* b_b = nullptr;
    const float* W_cls = nullptr;
    const float* b_cls = nullptr;

    for (int i = 0; i < n_in; i++) {
        int sz = in_sizes[i];
        const void* p = d_in[i];
        switch (sz) {
            case BATCH * TLEN:   inputs = p;                 break;
            case VOCAB * EMB:    emb    = (const float*)p;   break;
            case G4 * EMB:       W_ih   = (const float*)p;   break;
            case G4 * HID:       W_hh   = (const float*)p;   break;
            case VOCAB * HID:    W_cls  = (const float*)p;   break;
            case VOCAB:          b_cls  = (const float*)p;   break;
            case G4:
                if (!b_a) b_a = (const float*)p; else b_b = (const float*)p;
                break;
            default: break;
        }
    }
    if (!inputs || !emb || !W_ih || !W_hh || !b_a || !b_b || !W_cls || !b_cls)
        return;

    cudaFuncSetAttribute(k_lstm, cudaFuncAttributeMaxDynamicSharedMemorySize,
                         SMEM_BYTES);

    k_prep<<<VOCAB + 1, 128>>>((const unsigned int*)inputs, emb, W_ih, b_a, b_b);
    k_lstm<<<NBLK, NTHR, SMEM_BYTES>>>(inputs, W_hh, W_cls, b_cls,
                                       (float*)d_out);
}